// round 3
// baseline (speedup 1.0000x reference)
#include <cuda_runtime.h>
#include <math.h>
#include <stdint.h>

#define SEQ   2048
#define HID   2048
#define NHEADS 16
#define NKVH   4
#define HDIM   128
#define NEXP   8
#define IDIM   1024
#define ATT_SCALE 0.08838834764831845f   // 128^-0.5

// ---------------- scratch (device globals; no dynamic allocation) ----------------
__device__ float g_x1[SEQ * HID];                 // ln1 output
__device__ float g_q[SEQ * NHEADS * HDIM];        // Q
__device__ float g_k[SEQ * NKVH * HDIM];          // K
__device__ float g_v[SEQ * NKVH * HDIM];          // V
__device__ float g_attn[SEQ * NHEADS * HDIM];     // attention out (pre-wo)
__device__ float g_x3[SEQ * HID];                 // ln2 output
__device__ float g_moeh[2 * SEQ * IDIM];          // MoE hidden h = silu(g)*u
__device__ float g_tmp[2 * SEQ * IDIM];           // MoE raw g = X@W1
__device__ int   g_topidx[SEQ * 2];
__device__ float g_topw[SEQ * 2];
__device__ int   g_cnt[NEXP];
__device__ int   g_off[NEXP];
__device__ int   g_tok[NEXP * SEQ];
__device__ float g_tw[NEXP * SEQ];

// ---------------- helpers ----------------
__device__ __forceinline__ uint32_t f2tf(float x) {
  uint32_t r;
  asm("cvt.rna.tf32.f32 %0, %1;" : "=r"(r) : "f"(x));
  return r;
}

__device__ __forceinline__ void mma_tf32(float* c, const uint32_t* a, const uint32_t* b) {
  asm volatile(
      "mma.sync.aligned.m16n8k8.row.col.f32.tf32.tf32.f32 "
      "{%0,%1,%2,%3}, {%4,%5,%6,%7}, {%8,%9}, {%0,%1,%2,%3};"
      : "+f"(c[0]), "+f"(c[1]), "+f"(c[2]), "+f"(c[3])
      : "r"(a[0]), "r"(a[1]), "r"(a[2]), "r"(a[3]), "r"(b[0]), "r"(b[1]));
}

// ---------------- RMSNorm: one block per row ----------------
__global__ void rmsnorm_kernel(const float* __restrict__ x, const float* __restrict__ w,
                               float* __restrict__ y, int cols) {
  int row = blockIdx.x;
  const float* xr = x + (size_t)row * cols;
  float ss = 0.f;
  for (int i = threadIdx.x; i < cols; i += blockDim.x) { float v = xr[i]; ss += v * v; }
#pragma unroll
  for (int o = 16; o; o >>= 1) ss += __shfl_xor_sync(0xffffffffu, ss, o);
  __shared__ float sred[8];
  __shared__ float sscale;
  if ((threadIdx.x & 31) == 0) sred[threadIdx.x >> 5] = ss;
  __syncthreads();
  if (threadIdx.x == 0) {
    float t = 0.f;
#pragma unroll
    for (int i = 0; i < 8; i++) t += sred[i];
    sscale = rsqrtf(t / (float)cols + 1e-6f);
  }
  __syncthreads();
  float sc = sscale;
  float* yr = y + (size_t)row * cols;
  for (int i = threadIdx.x; i < cols; i += blockDim.x) yr[i] = xr[i] * sc * w[i];
}

// ---------------- tensor-core tf32 GEMM ----------------
// CTA tile 128x128, BK=32, 256 threads (8 warps as 2m x 4n), warp tile 64x32.
// MODE 0: C = A@B
// MODE 1: C = A@B + D
// MODE 2: A rows gathered via g_tok[e]; C[slot] = A@B        (MoE pass 1a: raw g)
// MODE 3: A rows gathered; C[slot] = silu(D[slot]) * (A@B)   (MoE pass 1b)
// MODE 4: A rows = slots (g_off[e]+m); atomicAdd C[token] += w * (A@B)  (MoE pass 2)
template <int MODE>
__global__ void __launch_bounds__(256, 1)
gemm_tc(const float* __restrict__ A, const float* __restrict__ B,
        const float* __restrict__ D, float* __restrict__ C, int N, int K) {
  __shared__ uint32_t As[128 * 36];   // As[m][k], stride 36 words (conflict-free frags)
  __shared__ uint32_t Bs[32 * 136];   // Bs[k][n], stride 136 words
  __shared__ int toks[128];

  const int tid = threadIdx.x;
  const int lane = tid & 31, wid = tid >> 5;
  const int wm = (wid >> 2) * 64, wn = (wid & 3) * 32;
  const int m0 = blockIdx.x * 128, n0 = blockIdx.y * 128;

  int e = 0, ne = 0, off = 0;
  if (MODE >= 2) {
    e = blockIdx.z;
    ne = g_cnt[e];
    off = g_off[e];
    if (m0 >= ne) return;
    B += (size_t)e * (size_t)K * (size_t)N;   // per-expert weight slab
    if (MODE == 2 || MODE == 3) {
      if (tid < 128) {
        int mm = m0 + tid;
        toks[tid] = g_tok[e * SEQ + (mm < ne ? mm : ne - 1)];
      }
      __syncthreads();
    }
  }

  // global pointers for the 4 A-chunks / 4 B-chunks this thread loads per K-slab
  const float* Arow[4];
  const float* Brow[4];
#pragma unroll
  for (int i = 0; i < 4; i++) {
    int idx = tid + i * 256;
    int r = idx >> 3;                  // 0..127
    int row;
    if (MODE == 2 || MODE == 3) row = toks[r];
    else if (MODE == 4) { int mm = m0 + r; if (mm >= ne) mm = ne - 1; row = off + mm; }
    else row = m0 + r;
    Arow[i] = A + (size_t)row * K + ((idx & 7) << 2);
    Brow[i] = B + (size_t)(idx >> 5) * N + n0 + ((idx & 31) << 2);
  }

  float acc[4][4][4];
#pragma unroll
  for (int a = 0; a < 4; a++)
#pragma unroll
    for (int b = 0; b < 4; b++)
#pragma unroll
      for (int c = 0; c < 4; c++) acc[a][b][c] = 0.f;

  float4 pa[4], pb[4];
#pragma unroll
  for (int i = 0; i < 4; i++) { pa[i] = *(const float4*)Arow[i]; pb[i] = *(const float4*)Brow[i]; }

  for (int k0 = 0; k0 < K; k0 += 32) {
    // store prefetched slab to smem (tf32-converted)
#pragma unroll
    for (int i = 0; i < 4; i++) {
      int idx = tid + i * 256;
      uint4 t;
      t.x = f2tf(pa[i].x); t.y = f2tf(pa[i].y); t.z = f2tf(pa[i].z); t.w = f2tf(pa[i].w);
      *(uint4*)&As[(idx >> 3) * 36 + ((idx & 7) << 2)] = t;
      uint4 u;
      u.x = f2tf(pb[i].x); u.y = f2tf(pb[i].y); u.z = f2tf(pb[i].z); u.w = f2tf(pb[i].w);
      *(uint4*)&Bs[(idx >> 5) * 136 + ((idx & 31) << 2)] = u;
    }
    __syncthreads();

    if (k0 + 32 < K) {
#pragma unroll
      for (int i = 0; i < 4; i++) {
        pa[i] = *(const float4*)(Arow[i] + (k0 + 32));
        pb[i] = *(const float4*)(Brow[i] + (size_t)(k0 + 32) * N);
      }
    }

#pragma unroll
    for (int ks = 0; ks < 4; ks++) {
      const int kb = ks * 8;
      uint32_t af[4][4], bf[4][2];
#pragma unroll
      for (int mt = 0; mt < 4; mt++) {
        int rb = wm + mt * 16 + (lane >> 2);
        int cc = kb + (lane & 3);
        af[mt][0] = As[rb * 36 + cc];
        af[mt][1] = As[(rb + 8) * 36 + cc];
        af[mt][2] = As[rb * 36 + cc + 4];
        af[mt][3] = As[(rb + 8) * 36 + cc + 4];
      }
#pragma unroll
      for (int nt = 0; nt < 4; nt++) {
        int cb = wn + nt * 8 + (lane >> 2);
        int rr = kb + (lane & 3);
        bf[nt][0] = Bs[rr * 136 + cb];
        bf[nt][1] = Bs[(rr + 4) * 136 + cb];
      }
#pragma unroll
      for (int mt = 0; mt < 4; mt++)
#pragma unroll
        for (int nt = 0; nt < 4; nt++) mma_tf32(acc[mt][nt], af[mt], bf[nt]);
    }
    __syncthreads();
  }

  // epilogue
#pragma unroll
  for (int mt = 0; mt < 4; mt++) {
#pragma unroll
    for (int half = 0; half < 2; half++) {
      int ml = wm + mt * 16 + (lane >> 2) + half * 8;
      if (MODE == 0 || MODE == 1) {
        size_t rowb = (size_t)(m0 + ml) * N;
#pragma unroll
        for (int nt = 0; nt < 4; nt++) {
          int nn = n0 + wn + nt * 8 + 2 * (lane & 3);
          float v0 = acc[mt][nt][half * 2], v1 = acc[mt][nt][half * 2 + 1];
          if (MODE == 1) { v0 += D[rowb + nn]; v1 += D[rowb + nn + 1]; }
          C[rowb + nn] = v0;
          C[rowb + nn + 1] = v1;
        }
      } else {
        int mm = m0 + ml;
        if (mm < ne) {
          if (MODE == 2) {
            size_t rowb = (size_t)(off + mm) * N;
#pragma unroll
            for (int nt = 0; nt < 4; nt++) {
              int nn = n0 + wn + nt * 8 + 2 * (lane & 3);
              C[rowb + nn] = acc[mt][nt][half * 2];
              C[rowb + nn + 1] = acc[mt][nt][half * 2 + 1];
            }
          } else if (MODE == 3) {
            size_t rowb = (size_t)(off + mm) * N;
#pragma unroll
            for (int nt = 0; nt < 4; nt++) {
              int nn = n0 + wn + nt * 8 + 2 * (lane & 3);
              float g0 = D[rowb + nn], g1 = D[rowb + nn + 1];
              float u0 = acc[mt][nt][half * 2], u1 = acc[mt][nt][half * 2 + 1];
              C[rowb + nn]     = g0 * u0 / (1.f + __expf(-g0));
              C[rowb + nn + 1] = g1 * u1 / (1.f + __expf(-g1));
            }
          } else {  // MODE 4
            int t = g_tok[e * SEQ + mm];
            float w = g_tw[e * SEQ + mm];
            size_t rowb = (size_t)t * HID;
#pragma unroll
            for (int nt = 0; nt < 4; nt++) {
              int nn = n0 + wn + nt * 8 + 2 * (lane & 3);
              atomicAdd(&C[rowb + nn], w * acc[mt][nt][half * 2]);
              atomicAdd(&C[rowb + nn + 1], w * acc[mt][nt][half * 2 + 1]);
            }
          }
        }
      }
    }
  }
}

// ---------------- partial RoPE (first RD=64 dims of each head), in place ----------------
__global__ void rope_kernel(float* __restrict__ x, const float* __restrict__ cp,
                            const float* __restrict__ sp, int nheads) {
  int idx = blockIdx.x * blockDim.x + threadIdx.x;
  int total = SEQ * nheads * 32;
  if (idx >= total) return;
  int d = idx & 31;
  int h = (idx >> 5) % nheads;
  int s = idx / (nheads * 32);
  size_t base = (size_t)s * nheads * HDIM + (size_t)h * HDIM + d;
  float a = x[base], b = x[base + 32];
  float c = cp[s * 64 + d], sn = sp[s * 64 + d];
  x[base]      = a * c - b * sn;
  x[base + 32] = b * c + a * sn;
}

// ---------------- causal flash attention, fp32, Br=Bc=64 ----------------
__global__ void flash_kernel(const float* __restrict__ Q, const float* __restrict__ Kp,
                             const float* __restrict__ Vp, float* __restrict__ O) {
  extern __shared__ float sm[];
  float* Qs = sm;                 // 64 x 132 (padded)
  float* Ks = Qs + 64 * 132;      // 64 x 132
  float* Vs = Ks + 64 * 132;      // 64 x 128
  float* Ps = Vs + 64 * 128;      // 64 x 64
  int qt = blockIdx.x, head = blockIdx.y;
  int kh = head >> 2;             // GQA: 4 query heads per KV head
  int tid = threadIdx.x, tx = tid & 15, ty = tid >> 4;
  int q0 = qt * 64;

  for (int i = tid; i < 64 * 32; i += 256) {
    int r = i >> 5, d4 = (i & 31) << 2;
    *(float4*)&Qs[r * 132 + d4] =
        *(const float4*)&Q[(size_t)(q0 + r) * (NHEADS * HDIM) + head * HDIM + d4];
  }

  float m[4], l[4], co[4][8];
#pragma unroll
  for (int i = 0; i < 4; i++) {
    m[i] = -3.0e38f; l[i] = 0.f;
#pragma unroll
    for (int c = 0; c < 8; c++) co[i][c] = 0.f;
  }

  for (int kt = 0; kt <= qt; kt++) {
    __syncthreads();
    int k0 = kt * 64;
    for (int i = tid; i < 64 * 32; i += 256) {
      int r = i >> 5, d4 = (i & 31) << 2;
      size_t gb = (size_t)(k0 + r) * (NKVH * HDIM) + kh * HDIM + d4;
      *(float4*)&Ks[r * 132 + d4] = *(const float4*)&Kp[gb];
      *(float4*)&Vs[r * 128 + d4] = *(const float4*)&Vp[gb];
    }
    __syncthreads();

    float sc[4][4] = {};
    for (int d = 0; d < 128; d += 4) {
      float4 aa[4], bb[4];
#pragma unroll
      for (int i = 0; i < 4; i++) aa[i] = *(const float4*)&Qs[((ty << 2) + i) * 132 + d];
#pragma unroll
      for (int j = 0; j < 4; j++) bb[j] = *(const float4*)&Ks[((tx << 2) + j) * 132 + d];
#pragma unroll
      for (int i = 0; i < 4; i++)
#pragma unroll
        for (int j = 0; j < 4; j++)
          sc[i][j] += aa[i].x * bb[j].x + aa[i].y * bb[j].y +
                      aa[i].z * bb[j].z + aa[i].w * bb[j].w;
    }

    bool diag = (kt == qt);
#pragma unroll
    for (int i = 0; i < 4; i++) {
      int r = (ty << 2) + i;
#pragma unroll
      for (int j = 0; j < 4; j++) {
        float v = sc[i][j] * ATT_SCALE;
        if (diag && ((tx << 2) + j) > r) v = -1e30f;
        sc[i][j] = v;
      }
      float mx = fmaxf(fmaxf(sc[i][0], sc[i][1]), fmaxf(sc[i][2], sc[i][3]));
#pragma unroll
      for (int o = 8; o; o >>= 1) mx = fmaxf(mx, __shfl_xor_sync(0xffffffffu, mx, o));
      float mn = fmaxf(m[i], mx);
      float corr = __expf(m[i] - mn);
      m[i] = mn;
      float rs = 0.f;
#pragma unroll
      for (int j = 0; j < 4; j++) {
        float p = __expf(sc[i][j] - mn);
        sc[i][j] = p; rs += p;
      }
#pragma unroll
      for (int o = 8; o; o >>= 1) rs += __shfl_xor_sync(0xffffffffu, rs, o);
      l[i] = l[i] * corr + rs;
#pragma unroll
      for (int c = 0; c < 8; c++) co[i][c] *= corr;
#pragma unroll
      for (int j = 0; j < 4; j++) Ps[r * 64 + (tx << 2) + j] = sc[i][j];
    }
    __syncthreads();

    for (int j = 0; j < 64; j++) {
      float4 v0 = *(const float4*)&Vs[j * 128 + (tx << 3)];
      float4 v1 = *(const float4*)&Vs[j * 128 + (tx << 3) + 4];
#pragma unroll
      for (int i = 0; i < 4; i++) {
        float p = Ps[((ty << 2) + i) * 64 + j];
        co[i][0] += p * v0.x; co[i][1] += p * v0.y;
        co[i][2] += p * v0.z; co[i][3] += p * v0.w;
        co[i][4] += p * v1.x; co[i][5] += p * v1.y;
        co[i][6] += p * v1.z; co[i][7] += p * v1.w;
      }
    }
  }

#pragma unroll
  for (int i = 0; i < 4; i++) {
    float inv = 1.f / l[i];
    int r = q0 + (ty << 2) + i;
#pragma unroll
    for (int c = 0; c < 8; c++)
      O[(size_t)r * (NHEADS * HDIM) + head * HDIM + (tx << 3) + c] = co[i][c] * inv;
  }
}

// ---------------- MoE gating: sigmoid, top-2, normalized weights (fp32) ----------------
__global__ void gate_kernel(const float* __restrict__ X, const float* __restrict__ GW,
                            const float* __restrict__ BE) {
  int t = blockIdx.x;
  const float* xr = X + (size_t)t * HID;
  float acc[NEXP];
#pragma unroll
  for (int e = 0; e < NEXP; e++) acc[e] = 0.f;
  for (int h = threadIdx.x; h < HID; h += blockDim.x) {
    float xv = xr[h];
    const float* g = GW + (size_t)h * NEXP;
#pragma unroll
    for (int e = 0; e < NEXP; e++) acc[e] += xv * g[e];
  }
#pragma unroll
  for (int e = 0; e < NEXP; e++)
#pragma unroll
    for (int o = 16; o; o >>= 1) acc[e] += __shfl_xor_sync(0xffffffffu, acc[e], o);
  __shared__ float ws[8][NEXP];
  if ((threadIdx.x & 31) == 0)
#pragma unroll
    for (int e = 0; e < NEXP; e++) ws[threadIdx.x >> 5][e] = acc[e];
  __syncthreads();
  if (threadIdx.x == 0) {
    float scv[NEXP], bi[NEXP];
#pragma unroll
    for (int e = 0; e < NEXP; e++) {
      float lg = 0.f;
#pragma unroll
      for (int wdx = 0; wdx < 8; wdx++) lg += ws[wdx][e];
      scv[e] = 1.f / (1.f + expf(-lg));
      bi[e] = scv[e] + BE[e];
    }
    int i0 = 0;
    for (int e = 1; e < NEXP; e++) if (bi[e] > bi[i0]) i0 = e;
    int i1 = -1;
    for (int e = 0; e < NEXP; e++) {
      if (e == i0) continue;
      if (i1 < 0 || bi[e] > bi[i1]) i1 = e;
    }
    float w0 = scv[i0], w1 = scv[i1];
    float ssum = fmaxf(w0 + w1, 1e-12f);
    g_topidx[t * 2] = i0; g_topidx[t * 2 + 1] = i1;
    g_topw[t * 2] = w0 / ssum; g_topw[t * 2 + 1] = w1 / ssum;
  }
}

__global__ void zero_cnt_kernel() {
  if (threadIdx.x < NEXP) g_cnt[threadIdx.x] = 0;
}

__global__ void route_kernel() {
  int s = blockIdx.x * blockDim.x + threadIdx.x;
  if (s >= SEQ * 2) return;
  int e = g_topidx[s];
  float w = g_topw[s];
  int p = atomicAdd(&g_cnt[e], 1);
  g_tok[e * SEQ + p] = s >> 1;
  g_tw[e * SEQ + p] = w;
}

__global__ void offsets_kernel() {
  if (threadIdx.x == 0) {
    int s = 0;
    for (int e = 0; e < NEXP; e++) { g_off[e] = s; s += g_cnt[e]; }
  }
}

// ---------------- launch ----------------
extern "C" void kernel_launch(void* const* d_in, const int* in_sizes, int n_in,
                              void* d_out, int out_size) {
  const float* hidden = (const float*)d_in[0];
  // d_in[1] = attention_mask: exact causal triu(-1e9) — implemented as causal attention
  const float* cosp = (const float*)d_in[2];
  const float* sinp = (const float*)d_in[3];
  const float* ln1  = (const float*)d_in[4];
  const float* ln2  = (const float*)d_in[5];
  const float* wq   = (const float*)d_in[6];
  const float* wk   = (const float*)d_in[7];
  const float* wv   = (const float*)d_in[8];
  const float* wo   = (const float*)d_in[9];
  const float* qn   = (const float*)d_in[10];
  const float* kn   = (const float*)d_in[11];
  const float* gw   = (const float*)d_in[12];
  const float* be   = (const float*)d_in[13];
  const float* w1   = (const float*)d_in[14];
  const float* w3   = (const float*)d_in[15];
  const float* w2   = (const float*)d_in[16];
  float* out = (float*)d_out;

  float *x1, *q, *k, *v, *attn, *x3, *moeh, *tmp;
  cudaGetSymbolAddress((void**)&x1, g_x1);
  cudaGetSymbolAddress((void**)&q, g_q);
  cudaGetSymbolAddress((void**)&k, g_k);
  cudaGetSymbolAddress((void**)&v, g_v);
  cudaGetSymbolAddress((void**)&attn, g_attn);
  cudaGetSymbolAddress((void**)&x3, g_x3);
  cudaGetSymbolAddress((void**)&moeh, g_moeh);
  cudaGetSymbolAddress((void**)&tmp, g_tmp);

  // 1) ln1
  rmsnorm_kernel<<<SEQ, 256>>>(hidden, ln1, x1, HID);
  // 2) QKV projections (tf32 tensor cores)
  gemm_tc<0><<<dim3(16, 16), 256>>>(x1, wq, nullptr, q, 2048, 2048);
  gemm_tc<0><<<dim3(16, 4), 256>>>(x1, wk, nullptr, k, 512, 2048);
  gemm_tc<0><<<dim3(16, 4), 256>>>(x1, wv, nullptr, v, 512, 2048);
  // 3) q/k norm (full-width, in place) + partial RoPE
  rmsnorm_kernel<<<SEQ, 256>>>(q, qn, q, 2048);
  rmsnorm_kernel<<<SEQ, 256>>>(k, kn, k, 512);
  rope_kernel<<<(SEQ * NHEADS * 32) / 256, 256>>>(q, cosp, sinp, NHEADS);
  rope_kernel<<<(SEQ * NKVH * 32) / 256, 256>>>(k, cosp, sinp, NKVH);
  // 4) causal flash attention (fp32)
  int fasmem = (64 * 132 * 2 + 64 * 128 + 64 * 64) * (int)sizeof(float);  // 116736 B
  cudaFuncSetAttribute(flash_kernel, cudaFuncAttributeMaxDynamicSharedMemorySize, fasmem);
  flash_kernel<<<dim3(32, NHEADS), 256, fasmem>>>(q, k, v, attn);
  // 5) wo + residual -> d_out (acts as res2)
  gemm_tc<1><<<dim3(16, 16), 256>>>(attn, wo, hidden, out, 2048, 2048);
  // 6) ln2
  rmsnorm_kernel<<<SEQ, 256>>>(out, ln2, x3, HID);
  // 7) gating + routing (fp32 — keeps top-k selection exact)
  gate_kernel<<<SEQ, 256>>>(x3, gw, be);
  zero_cnt_kernel<<<1, 32>>>();
  route_kernel<<<16, 256>>>();
  offsets_kernel<<<1, 32>>>();
  // 8) sparse MoE (tf32 tensor cores)
  gemm_tc<2><<<dim3(16, 8, 8), 256>>>(x3, w1, nullptr, tmp, IDIM, HID);   // raw g
  gemm_tc<3><<<dim3(16, 8, 8), 256>>>(x3, w3, tmp, moeh, IDIM, HID);      // silu(g)*u
  gemm_tc<4><<<dim3(16, 16, 8), 256>>>(moeh, w2, nullptr, out, HID, IDIM); // scatter-add
}

// round 4
// speedup vs baseline: 2.1515x; 2.1515x over previous
#include <cuda_runtime.h>
#include <math.h>
#include <stdint.h>

#define SEQ   2048
#define HID   2048
#define NHEADS 16
#define NKVH   4
#define HDIM   128
#define NEXP   8
#define IDIM   1024
#define NSLOT (2 * SEQ)
#define ATT_SCALE 0.08838834764831845f

__device__ float g_x1[SEQ * HID];
__device__ float g_q[SEQ * NHEADS * HDIM];
__device__ float g_k[SEQ * NKVH * HDIM];
__device__ float g_v[SEQ * NKVH * HDIM];
__device__ float g_attn[SEQ * NHEADS * HDIM];
__device__ float g_x3r[SEQ * HID];               // tf32-rounded (GEMM A)
__device__ float g_x3e[SEQ * HID];               // exact (gating)
__device__ float g_tmp[NSLOT * IDIM];            // raw g
__device__ float g_moeh[NSLOT * IDIM];           // silu(g)*u, rounded
__device__ float g_moeo[NSLOT * HID];            // per-slot expert output
__device__ int   g_topidx[SEQ * 2];
__device__ float g_topw[SEQ * 2];
__device__ int   g_pos[SEQ * 2];
__device__ int   g_cnt[NEXP];
__device__ int   g_off[NEXP];
__device__ int   g_tok[NEXP * SEQ];

__device__ __forceinline__ uint32_t f2tf(float x) {
  uint32_t r; asm("cvt.rna.tf32.f32 %0, %1;" : "=r"(r) : "f"(x)); return r;
}
__device__ __forceinline__ float roundtf(float x) { return __uint_as_float(f2tf(x)); }

__device__ __forceinline__ void mma_tf32(float* c, const uint32_t* a, const uint32_t* b) {
  asm volatile(
      "mma.sync.aligned.m16n8k8.row.col.f32.tf32.tf32.f32 "
      "{%0,%1,%2,%3}, {%4,%5,%6,%7}, {%8,%9}, {%0,%1,%2,%3};"
      : "+f"(c[0]), "+f"(c[1]), "+f"(c[2]), "+f"(c[3])
      : "r"(a[0]), "r"(a[1]), "r"(a[2]), "r"(a[3]), "r"(b[0]), "r"(b[1]));
}
__device__ __forceinline__ void cpasync16(uint32_t dst, const float* src) {
  asm volatile("cp.async.cg.shared.global [%0], [%1], 16;\n" :: "r"(dst), "l"(src));
}
__device__ __forceinline__ void cpcommit() { asm volatile("cp.async.commit_group;\n"); }
template <int NN> __device__ __forceinline__ void cpwait() {
  asm volatile("cp.async.wait_group %0;\n" :: "n"(NN));
}

// ---------------- RMSNorm (yr = tf32-rounded; ye = exact, optional) ----------------
__global__ void rmsnorm_kernel(const float* __restrict__ x, const float* __restrict__ w,
                               float* __restrict__ yr, float* __restrict__ ye, int cols) {
  int row = blockIdx.x;
  const float* xr = x + (size_t)row * cols;
  float ss = 0.f;
  for (int i = threadIdx.x; i < cols; i += blockDim.x) { float v = xr[i]; ss += v * v; }
#pragma unroll
  for (int o = 16; o; o >>= 1) ss += __shfl_xor_sync(0xffffffffu, ss, o);
  __shared__ float sred[8]; __shared__ float sscale;
  if ((threadIdx.x & 31) == 0) sred[threadIdx.x >> 5] = ss;
  __syncthreads();
  if (threadIdx.x == 0) {
    float t = 0.f;
#pragma unroll
    for (int i = 0; i < 8; i++) t += sred[i];
    sscale = rsqrtf(t / (float)cols + 1e-6f);
  }
  __syncthreads();
  float sc = sscale;
  for (int i = threadIdx.x; i < cols; i += blockDim.x) {
    float v = xr[i] * sc * w[i];
    yr[(size_t)row * cols + i] = roundtf(v);
    if (ye) ye[(size_t)row * cols + i] = v;
  }
}

// ---------------- fused rmsnorm + partial RoPE, in place, tf32-rounded ----------------
__global__ void rms_rope_kernel(float* __restrict__ x, const float* __restrict__ w,
                                const float* __restrict__ cp, const float* __restrict__ sp,
                                int nh) {
  int s = blockIdx.x, cols = nh * HDIM;
  float* xr = x + (size_t)s * cols;
  float ss = 0.f;
  for (int i = threadIdx.x; i < cols; i += blockDim.x) { float v = xr[i]; ss += v * v; }
#pragma unroll
  for (int o = 16; o; o >>= 1) ss += __shfl_xor_sync(0xffffffffu, ss, o);
  __shared__ float sred[8]; __shared__ float sscale;
  if ((threadIdx.x & 31) == 0) sred[threadIdx.x >> 5] = ss;
  __syncthreads();
  if (threadIdx.x == 0) {
    float t = 0.f;
#pragma unroll
    for (int i = 0; i < 8; i++) t += sred[i];
    sscale = rsqrtf(t / (float)cols + 1e-6f);
  }
  __syncthreads();
  float sc = sscale;
  for (int i = threadIdx.x; i < nh * 64; i += blockDim.x) {
    int h = i >> 6, sl = i & 63;
    if (sl < 32) {
      int i0 = h * HDIM + sl, i1 = i0 + 32;
      float a = xr[i0] * sc * w[i0], b = xr[i1] * sc * w[i1];
      float c = cp[s * 64 + sl], sn = sp[s * 64 + sl];
      xr[i0] = roundtf(a * c - b * sn);
      xr[i1] = roundtf(b * c + a * sn);
    } else {
      int i0 = h * HDIM + 32 + sl, i1 = i0 + 32;
      xr[i0] = roundtf(xr[i0] * sc * w[i0]);
      xr[i1] = roundtf(xr[i1] * sc * w[i1]);
    }
  }
}

// ---------------- tf32 GEMM, cp.async double-buffered, 128x128x32, 8 warps ----------------
// MODE 1: C = A@B + D (fp32 out).  MODE 2: gather rows, C[slot]=A@B.
// MODE 3: gather rows, C[slot]=round(silu(D[slot])*(A@B)).  MODE 4: slot rows, C[slot]=A@B.
// MODE 5: fused QKV (by<16 Q | <20 K | <24 V-rounded).
template <int MODE>
__global__ void __launch_bounds__(256, 2)
gemm_tc(const float* __restrict__ A, const float* __restrict__ B,
        const float* __restrict__ D, float* __restrict__ C, int N, int K,
        const float* __restrict__ B2, const float* __restrict__ B3,
        float* __restrict__ C2, float* __restrict__ C3) {
  extern __shared__ float smem[];
  float* As = smem;                      // [2][128*36]
  float* Bs = smem + 2 * 128 * 36;       // [2][32*136]
  __shared__ int toks[128];

  const int tid = threadIdx.x, lane = tid & 31, wid = tid >> 5;
  const int wm = (wid >> 2) * 64, wn = (wid & 3) * 32;
  const int m0 = blockIdx.x * 128, by = blockIdx.y;

  const float* Bp = B; int ldb = N; int n0 = by * 128;
  if (MODE == 5) {
    if (by < 16)      { Bp = B;  ldb = 2048; n0 = by * 128; }
    else if (by < 20) { Bp = B2; ldb = 512;  n0 = (by - 16) * 128; }
    else              { Bp = B3; ldb = 512;  n0 = (by - 20) * 128; }
  }

  int e = 0, ne = 0, off = 0;
  if (MODE >= 2 && MODE <= 4) {
    e = blockIdx.z; ne = g_cnt[e]; off = g_off[e];
    if (m0 >= ne) return;
    Bp += (size_t)e * (size_t)K * (size_t)ldb;
    if (MODE == 2 || MODE == 3) {
      if (tid < 128) {
        int mm = m0 + tid;
        toks[tid] = g_tok[e * SEQ + (mm < ne ? mm : ne - 1)];
      }
      __syncthreads();
    }
  }

  const float* Asrc[4]; const float* Bsrc[4];
  uint32_t Adst[4], Bdst[4];
  uint32_t sbase = (uint32_t)__cvta_generic_to_shared(smem);
#pragma unroll
  for (int i = 0; i < 4; i++) {
    int cid = tid + i * 256;
    int r = cid >> 3, kc = (cid & 7) << 2;
    int row;
    if (MODE == 2 || MODE == 3) row = toks[r];
    else if (MODE == 4) { int mm = m0 + r; if (mm >= ne) mm = ne - 1; row = off + mm; }
    else row = m0 + r;
    Asrc[i] = A + (size_t)row * K + kc;
    Adst[i] = sbase + (uint32_t)(r * 36 + kc) * 4u;
    int bk = cid >> 5, nc = (cid & 31) << 2;
    Bsrc[i] = Bp + (size_t)bk * ldb + n0 + nc;
    Bdst[i] = sbase + (uint32_t)(2 * 128 * 36 + bk * 136 + nc) * 4u;
  }
  const uint32_t stA = 128 * 36 * 4u, stB = 32 * 136 * 4u;

  float acc[4][4][4];
#pragma unroll
  for (int a = 0; a < 4; a++)
#pragma unroll
    for (int b = 0; b < 4; b++)
#pragma unroll
      for (int c = 0; c < 4; c++) acc[a][b][c] = 0.f;

  const int nslab = K >> 5;
#pragma unroll
  for (int i = 0; i < 4; i++) { cpasync16(Adst[i], Asrc[i]); cpasync16(Bdst[i], Bsrc[i]); }
  cpcommit();

  for (int s = 0; s < nslab; s++) {
    if (s + 1 < nslab) {
      int kofs = (s + 1) << 5;
      uint32_t so = ((s + 1) & 1) ? 1u : 0u;
#pragma unroll
      for (int i = 0; i < 4; i++) {
        cpasync16(Adst[i] + so * stA, Asrc[i] + kofs);
        cpasync16(Bdst[i] + so * stB, Bsrc[i] + (size_t)kofs * ldb);
      }
      cpcommit();
      cpwait<1>();
    } else cpwait<0>();
    __syncthreads();

    const float* Ab = As + (s & 1) * (128 * 36);
    const float* Bb = Bs + (s & 1) * (32 * 136);
#pragma unroll
    for (int ks = 0; ks < 4; ks++) {
      const int kb = ks * 8;
      uint32_t af[4][4], bf[4][2];
#pragma unroll
      for (int mt = 0; mt < 4; mt++) {
        int rb = wm + mt * 16 + (lane >> 2), cc = kb + (lane & 3);
        af[mt][0] = __float_as_uint(Ab[rb * 36 + cc]);
        af[mt][1] = __float_as_uint(Ab[(rb + 8) * 36 + cc]);
        af[mt][2] = __float_as_uint(Ab[rb * 36 + cc + 4]);
        af[mt][3] = __float_as_uint(Ab[(rb + 8) * 36 + cc + 4]);
      }
#pragma unroll
      for (int nt = 0; nt < 4; nt++) {
        int cb = wn + nt * 8 + (lane >> 2), rr = kb + (lane & 3);
        bf[nt][0] = f2tf(Bb[rr * 136 + cb]);
        bf[nt][1] = f2tf(Bb[(rr + 4) * 136 + cb]);
      }
#pragma unroll
      for (int mt = 0; mt < 4; mt++)
#pragma unroll
        for (int nt = 0; nt < 4; nt++) mma_tf32(acc[mt][nt], af[mt], bf[nt]);
    }
    __syncthreads();
  }

  float* Cp = C; int ldc = N; int cn0 = n0;
  if (MODE == 5) {
    if (by < 16)      { Cp = C;  ldc = 2048; }
    else if (by < 20) { Cp = C2; ldc = 512; }
    else              { Cp = C3; ldc = 512; }
  }
#pragma unroll
  for (int mt = 0; mt < 4; mt++) {
#pragma unroll
    for (int half = 0; half < 2; half++) {
      int ml = wm + mt * 16 + (lane >> 2) + half * 8;
      if (MODE == 1 || MODE == 5) {
        size_t rowb = (size_t)(m0 + ml) * ldc;
#pragma unroll
        for (int nt = 0; nt < 4; nt++) {
          int nn = cn0 + wn + nt * 8 + 2 * (lane & 3);
          float v0 = acc[mt][nt][half * 2], v1 = acc[mt][nt][half * 2 + 1];
          if (MODE == 1) { v0 += D[rowb + nn]; v1 += D[rowb + nn + 1]; }
          if (MODE == 5 && by >= 20) { v0 = roundtf(v0); v1 = roundtf(v1); }
          Cp[rowb + nn] = v0; Cp[rowb + nn + 1] = v1;
        }
      } else {
        int mm = m0 + ml;
        if (mm < ne) {
          size_t rowb = (size_t)(off + mm) * N;
#pragma unroll
          for (int nt = 0; nt < 4; nt++) {
            int nn = n0 + wn + nt * 8 + 2 * (lane & 3);
            float u0 = acc[mt][nt][half * 2], u1 = acc[mt][nt][half * 2 + 1];
            if (MODE == 3) {
              float g0 = D[rowb + nn], g1 = D[rowb + nn + 1];
              u0 = roundtf(g0 * u0 / (1.f + __expf(-g0)));
              u1 = roundtf(g1 * u1 / (1.f + __expf(-g1)));
            }
            C[rowb + nn] = u0; C[rowb + nn + 1] = u1;
          }
        }
      }
    }
  }
}

// ---------------- causal flash attention, tf32 mma, 4 warps, 64 q-rows/CTA ----------------
__global__ void __launch_bounds__(128) flash_tc(const float* __restrict__ Q,
                                                const float* __restrict__ Kp,
                                                const float* __restrict__ Vp,
                                                float* __restrict__ O) {
  extern __shared__ float sm[];
  float* Qs = sm;                 // [64][132]
  float* Ks = sm + 64 * 132;
  float* Vs = sm + 2 * 64 * 132;
  const int qt = gridDim.x - 1 - blockIdx.x;
  const int head = blockIdx.y, kh = head >> 2;
  const int tid = threadIdx.x, lane = tid & 31, w = tid >> 5;
  const int q0 = qt * 64, lr = lane >> 2, lc = lane & 3;

  for (int i = tid; i < 64 * 32; i += 128) {
    int r = i >> 5, c4 = (i & 31) << 2;
    *(float4*)&Qs[r * 132 + c4] = *(const float4*)&Q[(size_t)(q0 + r) * 2048 + head * HDIM + c4];
  }

  float mr0 = -3.0e38f, mr1 = -3.0e38f, li0 = 0.f, li1 = 0.f;
  float oacc[16][4];
#pragma unroll
  for (int i = 0; i < 16; i++)
#pragma unroll
    for (int j = 0; j < 4; j++) oacc[i][j] = 0.f;

  const int rloc = w * 16 + lr;
  const int gr0 = q0 + rloc, gr1 = gr0 + 8;

  for (int kt = 0; kt <= qt; kt++) {
    __syncthreads();
    for (int i = tid; i < 64 * 32; i += 128) {
      int r = i >> 5, c4 = (i & 31) << 2;
      size_t gb = (size_t)(kt * 64 + r) * 512 + kh * HDIM + c4;
      *(float4*)&Ks[r * 132 + c4] = *(const float4*)&Kp[gb];
      *(float4*)&Vs[r * 132 + c4] = *(const float4*)&Vp[gb];
    }
    __syncthreads();

    float sacc[8][4];
#pragma unroll
    for (int i = 0; i < 8; i++)
#pragma unroll
      for (int j = 0; j < 4; j++) sacc[i][j] = 0.f;
#pragma unroll
    for (int ks = 0; ks < 16; ks++) {
      const int kb = ks * 8;
      uint32_t a[4];
      a[0] = __float_as_uint(Qs[rloc * 132 + kb + lc]);
      a[1] = __float_as_uint(Qs[(rloc + 8) * 132 + kb + lc]);
      a[2] = __float_as_uint(Qs[rloc * 132 + kb + lc + 4]);
      a[3] = __float_as_uint(Qs[(rloc + 8) * 132 + kb + lc + 4]);
#pragma unroll
      for (int nt = 0; nt < 8; nt++) {
        int cb = nt * 8 + lr;
        uint32_t b[2];
        b[0] = __float_as_uint(Ks[cb * 132 + kb + lc]);
        b[1] = __float_as_uint(Ks[cb * 132 + kb + lc + 4]);
        mma_tf32(sacc[nt], a, b);
      }
    }

    const bool diag = (kt == qt);
#pragma unroll
    for (int nt = 0; nt < 8; nt++) {
      int gc = kt * 64 + nt * 8 + 2 * lc;
#pragma unroll
      for (int j = 0; j < 4; j++) {
        float v = sacc[nt][j] * ATT_SCALE;
        if (diag && (gc + (j & 1)) > ((j < 2) ? gr0 : gr1)) v = -1.0e30f;
        sacc[nt][j] = v;
      }
    }

    float mx0 = -3.0e38f, mx1 = -3.0e38f;
#pragma unroll
    for (int nt = 0; nt < 8; nt++) {
      mx0 = fmaxf(mx0, fmaxf(sacc[nt][0], sacc[nt][1]));
      mx1 = fmaxf(mx1, fmaxf(sacc[nt][2], sacc[nt][3]));
    }
    mx0 = fmaxf(mx0, __shfl_xor_sync(0xffffffffu, mx0, 1));
    mx0 = fmaxf(mx0, __shfl_xor_sync(0xffffffffu, mx0, 2));
    mx1 = fmaxf(mx1, __shfl_xor_sync(0xffffffffu, mx1, 1));
    mx1 = fmaxf(mx1, __shfl_xor_sync(0xffffffffu, mx1, 2));
    float mn0 = fmaxf(mr0, mx0), mn1 = fmaxf(mr1, mx1);
    float co0 = __expf(mr0 - mn0), co1 = __expf(mr1 - mn1);
    mr0 = mn0; mr1 = mn1;
    float rs0 = 0.f, rs1 = 0.f;
#pragma unroll
    for (int nt = 0; nt < 8; nt++) {
      sacc[nt][0] = __expf(sacc[nt][0] - mn0);
      sacc[nt][1] = __expf(sacc[nt][1] - mn0);
      sacc[nt][2] = __expf(sacc[nt][2] - mn1);
      sacc[nt][3] = __expf(sacc[nt][3] - mn1);
      rs0 += sacc[nt][0] + sacc[nt][1];
      rs1 += sacc[nt][2] + sacc[nt][3];
    }
    rs0 += __shfl_xor_sync(0xffffffffu, rs0, 1);
    rs0 += __shfl_xor_sync(0xffffffffu, rs0, 2);
    rs1 += __shfl_xor_sync(0xffffffffu, rs1, 1);
    rs1 += __shfl_xor_sync(0xffffffffu, rs1, 2);
    li0 = li0 * co0 + rs0; li1 = li1 * co1 + rs1;
#pragma unroll
    for (int i = 0; i < 16; i++) {
      oacc[i][0] *= co0; oacc[i][1] *= co0;
      oacc[i][2] *= co1; oacc[i][3] *= co1;
    }

#pragma unroll
    for (int kc = 0; kc < 8; kc++) {
      int src0 = (lane & ~3) | (lc >> 1), src1 = src0 + 2;
      float v00 = __shfl_sync(0xffffffffu, sacc[kc][0], src0);
      float v01 = __shfl_sync(0xffffffffu, sacc[kc][1], src0);
      float v10 = __shfl_sync(0xffffffffu, sacc[kc][0], src1);
      float v11 = __shfl_sync(0xffffffffu, sacc[kc][1], src1);
      float w00 = __shfl_sync(0xffffffffu, sacc[kc][2], src0);
      float w01 = __shfl_sync(0xffffffffu, sacc[kc][3], src0);
      float w10 = __shfl_sync(0xffffffffu, sacc[kc][2], src1);
      float w11 = __shfl_sync(0xffffffffu, sacc[kc][3], src1);
      uint32_t a[4];
      a[0] = f2tf((lc & 1) ? v01 : v00);
      a[1] = f2tf((lc & 1) ? w01 : w00);
      a[2] = f2tf((lc & 1) ? v11 : v10);
      a[3] = f2tf((lc & 1) ? w11 : w10);
      const int kb = kc * 8;
#pragma unroll
      for (int nt = 0; nt < 16; nt++) {
        int cb = nt * 8 + lr;
        uint32_t b[2];
        b[0] = __float_as_uint(Vs[(kb + lc) * 132 + cb]);
        b[1] = __float_as_uint(Vs[(kb + lc + 4) * 132 + cb]);
        mma_tf32(oacc[nt], a, b);
      }
    }
  }

  float inv0 = 1.f / li0, inv1 = 1.f / li1;
  size_t r0b = (size_t)gr0 * 2048 + head * HDIM, r1b = (size_t)gr1 * 2048 + head * HDIM;
#pragma unroll
  for (int nt = 0; nt < 16; nt++) {
    int nn = nt * 8 + 2 * lc;
    O[r0b + nn]     = roundtf(oacc[nt][0] * inv0);
    O[r0b + nn + 1] = roundtf(oacc[nt][1] * inv0);
    O[r1b + nn]     = roundtf(oacc[nt][2] * inv1);
    O[r1b + nn + 1] = roundtf(oacc[nt][3] * inv1);
  }
}

// ---------------- gating / routing ----------------
__global__ void gate_kernel(const float* __restrict__ X, const float* __restrict__ GW,
                            const float* __restrict__ BE) {
  int t = blockIdx.x;
  const float* xr = X + (size_t)t * HID;
  float acc[NEXP];
#pragma unroll
  for (int e = 0; e < NEXP; e++) acc[e] = 0.f;
  for (int h = threadIdx.x; h < HID; h += blockDim.x) {
    float xv = xr[h];
    const float* g = GW + (size_t)h * NEXP;
#pragma unroll
    for (int e = 0; e < NEXP; e++) acc[e] += xv * g[e];
  }
#pragma unroll
  for (int e = 0; e < NEXP; e++)
#pragma unroll
    for (int o = 16; o; o >>= 1) acc[e] += __shfl_xor_sync(0xffffffffu, acc[e], o);
  __shared__ float ws[8][NEXP];
  if ((threadIdx.x & 31) == 0)
#pragma unroll
    for (int e = 0; e < NEXP; e++) ws[threadIdx.x >> 5][e] = acc[e];
  __syncthreads();
  if (threadIdx.x == 0) {
    float scv[NEXP], bi[NEXP];
#pragma unroll
    for (int e = 0; e < NEXP; e++) {
      float lg = 0.f;
#pragma unroll
      for (int wdx = 0; wdx < 8; wdx++) lg += ws[wdx][e];
      scv[e] = 1.f / (1.f + expf(-lg));
      bi[e] = scv[e] + BE[e];
    }
    int i0 = 0;
    for (int e = 1; e < NEXP; e++) if (bi[e] > bi[i0]) i0 = e;
    int i1 = -1;
    for (int e = 0; e < NEXP; e++) {
      if (e == i0) continue;
      if (i1 < 0 || bi[e] > bi[i1]) i1 = e;
    }
    float w0 = scv[i0], w1 = scv[i1];
    float ssum = fmaxf(w0 + w1, 1e-12f);
    g_topidx[t * 2] = i0; g_topidx[t * 2 + 1] = i1;
    g_topw[t * 2] = w0 / ssum; g_topw[t * 2 + 1] = w1 / ssum;
  }
}

__global__ void zero_cnt_kernel() { if (threadIdx.x < NEXP) g_cnt[threadIdx.x] = 0; }

__global__ void route_kernel() {
  int s = blockIdx.x * blockDim.x + threadIdx.x;
  if (s >= SEQ * 2) return;
  int e = g_topidx[s];
  int p = atomicAdd(&g_cnt[e], 1);
  g_pos[s] = p;
  g_tok[e * SEQ + p] = s >> 1;
}

__global__ void offsets_kernel() {
  if (threadIdx.x == 0) {
    int s = 0;
    for (int e = 0; e < NEXP; e++) { g_off[e] = s; s += g_cnt[e]; }
  }
}

// ---------------- MoE combine: out[t] += w0*moeo[slot0] + w1*moeo[slot1] ----------------
__global__ void combine_kernel(float* __restrict__ out, const float* __restrict__ moeo) {
  int t = blockIdx.x;
  int s0 = g_off[g_topidx[t * 2]] + g_pos[t * 2];
  int s1 = g_off[g_topidx[t * 2 + 1]] + g_pos[t * 2 + 1];
  float w0 = g_topw[t * 2], w1 = g_topw[t * 2 + 1];
  const float* r0 = moeo + (size_t)s0 * HID;
  const float* r1 = moeo + (size_t)s1 * HID;
  float* o = out + (size_t)t * HID;
  for (int i = threadIdx.x; i < HID; i += blockDim.x)
    o[i] += w0 * r0[i] + w1 * r1[i];
}

// ---------------- launch ----------------
extern "C" void kernel_launch(void* const* d_in, const int* in_sizes, int n_in,
                              void* d_out, int out_size) {
  const float* hidden = (const float*)d_in[0];
  const float* cosp = (const float*)d_in[2];
  const float* sinp = (const float*)d_in[3];
  const float* ln1  = (const float*)d_in[4];
  const float* ln2  = (const float*)d_in[5];
  const float* wq   = (const float*)d_in[6];
  const float* wk   = (const float*)d_in[7];
  const float* wv   = (const float*)d_in[8];
  const float* wo   = (const float*)d_in[9];
  const float* qn   = (const float*)d_in[10];
  const float* kn   = (const float*)d_in[11];
  const float* gw   = (const float*)d_in[12];
  const float* be   = (const float*)d_in[13];
  const float* w1   = (const float*)d_in[14];
  const float* w3   = (const float*)d_in[15];
  const float* w2   = (const float*)d_in[16];
  float* out = (float*)d_out;

  float *x1, *q, *k, *v, *attn, *x3r, *x3e, *tmp, *moeh, *moeo;
  cudaGetSymbolAddress((void**)&x1, g_x1);
  cudaGetSymbolAddress((void**)&q, g_q);
  cudaGetSymbolAddress((void**)&k, g_k);
  cudaGetSymbolAddress((void**)&v, g_v);
  cudaGetSymbolAddress((void**)&attn, g_attn);
  cudaGetSymbolAddress((void**)&x3r, g_x3r);
  cudaGetSymbolAddress((void**)&x3e, g_x3e);
  cudaGetSymbolAddress((void**)&tmp, g_tmp);
  cudaGetSymbolAddress((void**)&moeh, g_moeh);
  cudaGetSymbolAddress((void**)&moeo, g_moeo);

  const int GS = (2 * 128 * 36 + 2 * 32 * 136) * 4;  // 71680 B
  cudaFuncSetAttribute(gemm_tc<1>, cudaFuncAttributeMaxDynamicSharedMemorySize, GS);
  cudaFuncSetAttribute(gemm_tc<2>, cudaFuncAttributeMaxDynamicSharedMemorySize, GS);
  cudaFuncSetAttribute(gemm_tc<3>, cudaFuncAttributeMaxDynamicSharedMemorySize, GS);
  cudaFuncSetAttribute(gemm_tc<4>, cudaFuncAttributeMaxDynamicSharedMemorySize, GS);
  cudaFuncSetAttribute(gemm_tc<5>, cudaFuncAttributeMaxDynamicSharedMemorySize, GS);
  const int FS = 3 * 64 * 132 * 4;                   // 101376 B
  cudaFuncSetAttribute(flash_tc, cudaFuncAttributeMaxDynamicSharedMemorySize, FS);

  rmsnorm_kernel<<<SEQ, 256>>>(hidden, ln1, x1, nullptr, HID);
  gemm_tc<5><<<dim3(16, 24), 256, GS>>>(x1, wq, nullptr, q, 2048, 2048, wk, wv, k, v);
  rms_rope_kernel<<<SEQ, 256>>>(q, qn, cosp, sinp, NHEADS);
  rms_rope_kernel<<<SEQ, 256>>>(k, kn, cosp, sinp, NKVH);
  flash_tc<<<dim3(32, NHEADS), 128, FS>>>(q, k, v, attn);
  gemm_tc<1><<<dim3(16, 16), 256, GS>>>(attn, wo, hidden, out, 2048, 2048,
                                        nullptr, nullptr, nullptr, nullptr);
  rmsnorm_kernel<<<SEQ, 256>>>(out, ln2, x3r, x3e, HID);
  gate_kernel<<<SEQ, 256>>>(x3e, gw, be);
  zero_cnt_kernel<<<1, 32>>>();
  route_kernel<<<16, 256>>>();
  offsets_kernel<<<1, 32>>>();
  gemm_tc<2><<<dim3(16, 8, 8), 256, GS>>>(x3r, w1, nullptr, tmp, IDIM, HID,
                                          nullptr, nullptr, nullptr, nullptr);
  gemm_tc<3><<<dim3(16, 8, 8), 256, GS>>>(x3r, w3, tmp, moeh, IDIM, HID,
                                          nullptr, nullptr, nullptr, nullptr);
  gemm_tc<4><<<dim3(16, 16, 8), 256, GS>>>(moeh, w2, nullptr, moeo, HID, IDIM,
                                           nullptr, nullptr, nullptr, nullptr);
  combine_kernel<<<SEQ, 256>>>(out, moeo);
}